// round 17
// baseline (speedup 1.0000x reference)
#include <cuda_runtime.h>
#include <cuda_bf16.h>
#include <cstdint>

// Problem constants (match reference_code)
#define NV       1000000
#define NE       3000000
#define IMG_H    1024
#define IMG_W    1024
#define HW       (IMG_H * IMG_W)       // 1048576
#define MAX_DEPTH 10.0f
#define CREGU    2000.0f

#define B        256
#define NQ       (NV / 4)                      // 250000 vertex quads
#define MEAN_BLOCKS  ((NQ + B - 1) / B)        // 977
#define PROJ_BLOCKS  ((NQ + B - 1) / B)        // 977
#define EDGE_BLOCKS  ((NE / 2 + B - 1) / B)    // 5860
#define EN_BLOCKS    ((HW / 4) / B)            // 1024

// ---------------- scratch (device globals; zero-initialized at load) --------
// g_dmax[p] holds max over vertices of (MAX_DEPTH - zvalid) as float bits.
// Empty state = 0 (load-time zeros; K4 restores zeros each replay).
//   depth = MAX_DEPTH - max(g_dmax, 0-losers)  ==  clip(min zvalid, 0, 10).
__device__ int      g_dmax[HW];       // 4 MB    scatter-max target (self-zeroing)
__device__ float4   g_dv4[NV];        // 16 MB   {dvx, dvy, dvz, 0}
__device__ float4   g_neigh4[NV];     // 16 MB   {nx, ny, nz, deg} (self-zeroing)
__device__ double   g_sums[3];        // vertex component sums (self-zeroing)
__device__ double   g_acc;            // total energy accumulator (self-zeroing)
__device__ unsigned g_done;           // last-block counter (self-zeroing)

// ---------------- float block reduce (shared) --------------------------------
__device__ __forceinline__ float block_reduce_f(float v) {
    __shared__ float sh[B];
    int t = threadIdx.x;
    sh[t] = v;
    __syncthreads();
    for (int s = blockDim.x >> 1; s > 32; s >>= 1) {
        if (t < s) sh[t] += sh[t + s];
        __syncthreads();
    }
    if (t < 32) {
        float x = sh[t] + sh[t + 32];
        #pragma unroll
        for (int o = 16; o > 0; o >>= 1)
            x += __shfl_down_sync(0xFFFFFFFFu, x, o);
        if (t == 0) sh[0] = x;
    }
    __syncthreads();
    return sh[0];
}

// ---------------- K1: vertex mean partials (12 MB read only) -----------------
__global__ void k_mean(const float4* __restrict__ verts4) {
    int i = blockIdx.x * blockDim.x + threadIdx.x;
    float sx = 0.0f, sy = 0.0f, sz = 0.0f;
    if (i < NQ) {
        float4 a = verts4[3 * i + 0];   // v0.x v0.y v0.z v1.x
        float4 b = verts4[3 * i + 1];   // v1.y v1.z v2.x v2.y
        float4 c = verts4[3 * i + 2];   // v2.z v3.x v3.y v3.z
        sx = a.x + a.w + b.z + c.y;
        sy = a.y + b.x + b.w + c.z;
        sz = a.z + b.y + c.x + c.w;
    }
    float bx = block_reduce_f(sx);
    __syncthreads();
    float by = block_reduce_f(sy);
    __syncthreads();
    float bz = block_reduce_f(sz);
    if (threadIdx.x == 0) {
        atomicAdd(&g_sums[0], (double)bx);
        atomicAdd(&g_sums[1], (double)by);
        atomicAdd(&g_sums[2], (double)bz);
    }
}

// ---------------- K2: dv + project via atomicMax(10 - z) ---------------------
// No depth fill needed: empty sentinel is 0, restored by K4 each replay.
__global__ void k_pre_proj(const float4* __restrict__ verts4,
                           const float4* __restrict__ vref4,
                           const float* __restrict__ quat,
                           const float* __restrict__ trans,
                           const float* __restrict__ intr,
                           const float* __restrict__ extr) {
    int i = blockIdx.x * blockDim.x + threadIdx.x;   // < 250000
    if (i >= NQ) return;

    float4 a = verts4[3 * i + 0];
    float4 b = verts4[3 * i + 1];
    float4 c = verts4[3 * i + 2];
    float4 ra = vref4[3 * i + 0];
    float4 rb = vref4[3 * i + 1];
    float4 rc = vref4[3 * i + 2];

    g_dv4[4 * i + 0] = make_float4(a.x - ra.x, a.y - ra.y, a.z - ra.z, 0.0f);
    g_dv4[4 * i + 1] = make_float4(a.w - ra.w, b.x - rb.x, b.y - rb.y, 0.0f);
    g_dv4[4 * i + 2] = make_float4(b.z - rb.z, b.w - rb.w, c.x - rc.x, 0.0f);
    g_dv4[4 * i + 3] = make_float4(c.y - rc.y, c.z - rc.z, c.w - rc.w, 0.0f);

    // ---- projection (mean ready from K1) ----
    float qx = quat[0], qy = quat[1], qz = quat[2], qw = quat[3];
    float qn = 1.0f / sqrtf(qx * qx + qy * qy + qz * qz + qw * qw);
    qx *= qn; qy *= qn; qz *= qn; qw *= qn;

    float mx = (float)(g_sums[0] / (double)NV);
    float my = (float)(g_sums[1] / (double)NV);
    float mz = (float)(g_sums[2] / (double)NV);

    float vxs[4] = {a.x, a.w, b.z, c.y};
    float vys[4] = {a.y, b.x, b.w, c.z};
    float vzs[4] = {a.z, b.y, c.x, c.w};

    #pragma unroll
    for (int k = 0; k < 4; k++) {
        float vx = vxs[k] - mx;
        float vy = vys[k] - my;
        float vz = vzs[k] - mz;

        // qrot: v + 2*(w*uv + uuv), uv = qv x v, uuv = qv x uv
        float uvx = qy * vz - qz * vy;
        float uvy = qz * vx - qx * vz;
        float uvz = qx * vy - qy * vx;
        float uuvx = qy * uvz - qz * uvy;
        float uuvy = qz * uvx - qx * uvz;
        float uuvz = qx * uvy - qy * uvx;
        float tx = vx + 2.0f * (qw * uvx + uuvx) + trans[0];
        float ty = vy + 2.0f * (qw * uvy + uuvy) + trans[1];
        float tz = vz + 2.0f * (qw * uvz + uuvz) + trans[2];

        // p_cam = E[:, :3] @ v_t + E[:, 3]   (extr row-major 3x4)
        float p0 = extr[0] * tx + extr[1] * ty + extr[2]  * tz + extr[3];
        float p1 = extr[4] * tx + extr[5] * ty + extr[6]  * tz + extr[7];
        float p2 = extr[8] * tx + extr[9] * ty + extr[10] * tz + extr[11];

        // proj = K @ p_cam (intr row-major 3x3)
        float pr0 = intr[0] * p0 + intr[1] * p1 + intr[2] * p2;
        float pr1 = intr[3] * p0 + intr[4] * p1 + intr[5] * p2;
        float pr2 = intr[6] * p0 + intr[7] * p1 + intr[8] * p2;

        float u = pr0 / pr2;
        float v = pr1 / pr2;

        float fx = rintf(u);                  // round half to even == jnp.round
        float fy = rintf(v);
        fx = fminf(fmaxf(fx, 0.0f), (float)(IMG_W - 1));
        fy = fminf(fmaxf(fy, 0.0f), (float)(IMG_H - 1));
        int flat = (int)fy * IMG_W + (int)fx;

        float zvalid = (p2 > 0.0f) ? p2 : MAX_DEPTH;   // DEPTH_SCALE = 1
        float g = MAX_DEPTH - zvalid;   // >=0 wins; negative (z>10) loses to 0
        // positive floats monotonic as signed int; negative floats < 0 as int
        atomicMax(&g_dmax[flat], __float_as_int(g));
    }
}

// ---------------- K3: edge accumulation (2 edges/thread, v4 reductions) -----
__global__ void k_edge(const int4* __restrict__ edges2) {
    int e = blockIdx.x * blockDim.x + threadIdx.x;   // < NE/2
    if (e >= NE / 2) return;
    int4 p = edges2[e];                   // (s0, d0, s1, d1), 16B coalesced
    float4 dv0 = g_dv4[p.y];
    float4 dv1 = g_dv4[p.w];
    asm volatile(
        "red.global.add.v4.f32 [%0], {%1, %2, %3, %4};"
        :: "l"(&g_neigh4[p.x]), "f"(dv0.x), "f"(dv0.y), "f"(dv0.z), "f"(1.0f)
        : "memory");
    asm volatile(
        "red.global.add.v4.f32 [%0], {%1, %2, %3, %4};"
        :: "l"(&g_neigh4[p.z]), "f"(dv1.x), "f"(dv1.y), "f"(dv1.z), "f"(1.0f)
        : "memory");
}

// ---------------- K4: energy + restore scratch + last-block finalize ---------
__global__ void k_energy_final(const float4* __restrict__ hand4,
                               float* __restrict__ out) {
    int i = blockIdx.x * blockDim.x + threadIdx.x;   // < 262144
    float4 z4 = make_float4(0.0f, 0.0f, 0.0f, 0.0f);

    // depth energy: depth = MAX_DEPTH - t (t = stored max(10 - zvalid), 0 if empty)
    float4 t = ((const float4*)g_dmax)[i];
    ((float4*)g_dmax)[i] = z4;            // restore empty sentinel for next replay
    float4 h = hand4[i];
    float d0 = (MAX_DEPTH - t.x) - h.x;
    float d1 = (MAX_DEPTH - t.y) - h.y;
    float d2 = (MAX_DEPTH - t.z) - h.z;
    float d3 = (MAX_DEPTH - t.w) - h.w;
    float local = d0 * d0 + d1 * d1 + d2 * d2 + d3 * d3;

    if (i < NQ) {
        #pragma unroll
        for (int k = 0; k < 4; k++) {
            float4 dv = g_dv4[4 * i + k];
            float4 nb = g_neigh4[4 * i + k];
            g_neigh4[4 * i + k] = z4;     // restore zeros for next replay
            float dg = nb.w;
            float lx = dg * dv.x - nb.x;
            float ly = dg * dv.y - nb.y;
            float lz = dg * dv.z - nb.z;
            local += CREGU * (lx * lx + ly * ly + lz * lz);
        }
    }
    float b = block_reduce_f(local);
    if (threadIdx.x == 0) {
        atomicAdd(&g_acc, (double)b);
        __threadfence();
        unsigned tk = atomicAdd(&g_done, 1u);
        if (tk == gridDim.x - 1) {     // last block: finalize + re-zero
            out[0] = (float)g_acc;
            g_acc = 0.0;
            g_sums[0] = 0.0; g_sums[1] = 0.0; g_sums[2] = 0.0;
            g_done = 0u;
        }
    }
}

// ---------------- launch -----------------------------------------------------
extern "C" void kernel_launch(void* const* d_in, const int* in_sizes, int n_in,
                              void* d_out, int out_size) {
    const float4* verts4 = (const float4*)d_in[0];
    const float4* vref4  = (const float4*)d_in[1];
    const float*  quat   = (const float*)d_in[2];
    const float*  trans  = (const float*)d_in[3];
    const float4* hand4  = (const float4*)d_in[4];
    const float*  intr   = (const float*)d_in[5];
    const float*  extr   = (const float*)d_in[6];
    const int4*   edges2 = (const int4*)d_in[7];
    float* out = (float*)d_out;

    k_mean<<<MEAN_BLOCKS, B>>>(verts4);
    k_pre_proj<<<PROJ_BLOCKS, B>>>(verts4, vref4, quat, trans, intr, extr);
    k_edge<<<EDGE_BLOCKS, B>>>(edges2);
    k_energy_final<<<EN_BLOCKS, B>>>(hand4, out);
}